// round 17
// baseline (speedup 1.0000x reference)
#include <cuda_runtime.h>
#include <cuda_bf16.h>
#include <cuda_fp16.h>
#include <cstdint>

#define IN_DIM   32
#define NB       11
#define FPAD     10                    // basis cols per feature (sin/cos only)
#define HID      64
#define TILE_M   128
#define NCHUNK   2
#define KSTEPS   10                    // k16-steps per chunk (160 cols)
#define KS_TOTAL 20
#define THREADS  256
#define NCTAS    296                   // 148 SMs x 2 resident CTAs
#define MAXROWS  131072

#define A_STRIDE_B  336                // smem bytes per A row per chunk (conflict-free)
#define ROW_BYTES   640                // gmem bytes per row (320 halves)
#define CHUNK_GB    320                // gmem bytes per row per chunk

// ---- SMEM: double-buffered A (fp16) ----
#define ABUF_BYTES  (TILE_M * A_STRIDE_B)       // 43008
#define SMEM_TOTAL  (2 * ABUF_BYTES)            // 86016

#define BFRAG_BYTES (KS_TOTAL * 8 * 32 * 8)     // 40960

__device__ __align__(16) unsigned char g_A[(long)MAXROWS * ROW_BYTES]; // 84 MB
__device__ __align__(16) unsigned char g_Bh[BFRAG_BYTES];   // fp16 B fragments
__device__ float g_c0[HID];            // sum_f (W[f][0][:] + b[f][:]), fp32 exact

// ---------------------------------------------------------------- helpers
__device__ __forceinline__ uint32_t smem_u32(const void* p) {
    uint32_t a;
    asm("{ .reg .u64 t; cvta.to.shared.u64 t, %1; cvt.u32.u64 %0, t; }"
        : "=r"(a) : "l"(p));
    return a;
}
__device__ __forceinline__ void ldm4(uint32_t* r, uint32_t a) {
    asm volatile("ldmatrix.sync.aligned.m8n8.x4.shared.b16 {%0,%1,%2,%3}, [%4];"
                 : "=r"(r[0]), "=r"(r[1]), "=r"(r[2]), "=r"(r[3]) : "r"(a));
}
__device__ __forceinline__ void sts128(uint32_t a, uint4 v) {
    asm volatile("st.shared.v4.b32 [%0], {%1,%2,%3,%4};"
                 :: "r"(a), "r"(v.x), "r"(v.y), "r"(v.z), "r"(v.w) : "memory");
}
__device__ __forceinline__ void mma16816(float* d, const uint32_t* a, const uint32_t* b) {
    asm volatile(
        "mma.sync.aligned.m16n8k16.row.col.f32.f16.f16.f32 "
        "{%0,%1,%2,%3}, {%4,%5,%6,%7}, {%8,%9}, {%0,%1,%2,%3};"
        : "+f"(d[0]), "+f"(d[1]), "+f"(d[2]), "+f"(d[3])
        : "r"(a[0]), "r"(a[1]), "r"(a[2]), "r"(a[3]), "r"(b[0]), "r"(b[1]));
}

// sin/cos harmonics 1..5 of xv (MUFU + product recurrence) — identical to R13
__device__ __forceinline__ void sincos_harm(float xv, float* v) {
    float s1, c1;
    __sincosf(xv, &s1, &c1);
    float s2 = 2.f * s1 * c1;
    float c2 = fmaf(c1, c1, -(s1 * s1));
    float s3 = s2 * c1 + c2 * s1;
    float c3 = c2 * c1 - s2 * s1;
    float s4 = s3 * c1 + c3 * s1;
    float c4 = c3 * c1 - s3 * s1;
    float s5 = s4 * c1 + c4 * s1;
    float c5 = c4 * c1 - s4 * s1;
    v[0] = s1; v[1] = c1; v[2] = s2; v[3] = c2; v[4] = s3;
    v[5] = c3; v[6] = s4; v[7] = c4; v[8] = s5; v[9] = c5;
}

// ---------------------------------------------------------------- prep kernel
// B fragments (fp16, mma layout) + c0. Same as R13.
__global__ void prep_kernel(const float* __restrict__ W, const float* __restrict__ bias) {
    int idx = blockIdx.x * blockDim.x + threadIdx.x;
    if (idx < HID) {
        float s = 0.f;
        #pragma unroll
        for (int f = 0; f < IN_DIM; f++)
            s += W[(f * NB) * HID + idx] + bias[f * HID + idx];
        g_c0[idx] = s;
    }
    if (idx >= KS_TOTAL * 8 * 32) return;
    int t   = idx & 31;
    int nt  = (idx >> 5) & 7;
    int ksg = idx >> 8;
    int n     = nt * 8 + (t >> 2);
    int kbase = ksg * 16 + (t & 3) * 2;

    uint32_t hi[2];
    #pragma unroll
    for (int half = 0; half < 2; half++) {
        int k0 = kbase + half * 8;
        int k1 = k0 + 1;
        float v0 = W[((k0 / FPAD) * NB + (k0 % FPAD) + 1) * HID + n];
        float v1 = W[((k1 / FPAD) * NB + (k1 % FPAD) + 1) * HID + n];
        __half2 h2 = __floats2half2_rn(v0, v1);
        hi[half] = *(uint32_t*)&h2;
    }
    *(uint2*)(g_Bh + idx * 8) = make_uint2(hi[0], hi[1]);
}

// ---------------------------------------------------------------- gen kernel
// Writes A (fp16 basis) for all rows to g_A[row][320 halves], f-major.
// Job = (row, feature-pair fp in [0,16)): 40 bytes at row*640 + fp*40.
__global__ void __launch_bounds__(THREADS)
gen_kernel(const float* __restrict__ x, int n_rows)
{
    const int total = n_rows * 16;
    for (int job = blockIdx.x * THREADS + threadIdx.x; job < total;
         job += gridDim.x * THREADS) {
        const int r  = job >> 4;
        const int fp = job & 15;

        float2 xv = __ldg((const float2*)(x + (long)r * IN_DIM + fp * 2));
        float v[20];
        sincos_harm(xv.x, v);
        sincos_harm(xv.y, v + 10);

        uint2* dst = (uint2*)(g_A + (long)r * ROW_BYTES + fp * 40);
        #pragma unroll
        for (int p = 0; p < 5; p++) {
            __half2 a = __floats2half2_rn(v[4 * p + 0], v[4 * p + 1]);
            __half2 b = __floats2half2_rn(v[4 * p + 2], v[4 * p + 3]);
            dst[p] = make_uint2(*(uint32_t*)&a, *(uint32_t*)&b);
        }
    }
}

// ---------------------------------------------------------------- gemm kernel
__global__ void __launch_bounds__(THREADS, 2)
gemm_kernel(float* __restrict__ out, int n_rows, int ntiles)
{
    extern __shared__ __align__(16) unsigned char smem[];
    const uint32_t sbase = smem_u32(smem);
    const int tid  = threadIdx.x;
    const int lane = tid & 31;
    const int wid  = tid >> 5;
    const int mw   = wid & 3;    // M warp: rows mw*32
    const int nw   = wid >> 2;   // N warp: cols nw*32

    const int lrow = lane & 15, lcol = lane >> 4;
    const uint32_t aOff = (uint32_t)(mw * 32 + lrow) * A_STRIDE_B + lcol * 16;

    // epilogue constant
    float c0v[4][2];
    #pragma unroll
    for (int j = 0; j < 4; j++) {
        const int col = nw * 32 + j * 8 + (lane & 3) * 2;
        c0v[j][0] = __ldg(&g_c0[col]);
        c0v[j][1] = __ldg(&g_c0[col + 1]);
    }

    // staging offsets: this thread copies 16B units idx = tid + 256*k, k<10
    // r = idx/20, cc = idx%20; src: r*640 + ch*320 + cc*16 ; dst: r*336 + cc*16
    int srow[10], scc[10];
    #pragma unroll
    for (int k = 0; k < 10; k++) {
        const int idx = tid + THREADS * k;
        srow[k] = idx / 20;
        scc[k]  = idx % 20;
    }

    // prologue: load + store chunk 0 of first tile
    int buf = 0;
    if (blockIdx.x < (unsigned)ntiles) {
        const long gbase = (long)blockIdx.x * TILE_M * ROW_BYTES;
        #pragma unroll
        for (int k = 0; k < 10; k++) {
            uint4 v = __ldg((const uint4*)(g_A + gbase + (long)srow[k] * ROW_BYTES + scc[k] * 16));
            sts128(sbase + (uint32_t)(srow[k] * A_STRIDE_B + scc[k] * 16), v);
        }
    }
    __syncthreads();

    for (int tile = blockIdx.x; tile < ntiles; tile += gridDim.x) {
        const long tile_row0 = (long)tile * TILE_M;

        float d[2][4][4];
        #pragma unroll
        for (int mt = 0; mt < 2; mt++)
            #pragma unroll
            for (int j = 0; j < 4; j++)
                #pragma unroll
                for (int e = 0; e < 4; e++) d[mt][j][e] = 0.f;

        for (int ch = 0; ch < NCHUNK; ch++) {
            // issue loads for NEXT chunk (latency hidden behind mma below)
            const int  ntile = (ch < NCHUNK - 1) ? tile : tile + gridDim.x;
            const int  nch   = (ch < NCHUNK - 1) ? ch + 1 : 0;
            const bool have_next = (ntile < ntiles);
            uint4 stage[10];
            if (have_next) {
                const long gbase = (long)ntile * TILE_M * ROW_BYTES + nch * CHUNK_GB;
                #pragma unroll
                for (int k = 0; k < 10; k++)
                    stage[k] = __ldg((const uint4*)(g_A + gbase + (long)srow[k] * ROW_BYTES + scc[k] * 16));
            }

            // === mma on current buffer: 10 k-steps x (2 mt x 4 nt) ===
            const uint32_t aBase = sbase + buf * ABUF_BYTES + aOff;
            #pragma unroll
            for (int s = 0; s < KSTEPS; s++) {
                uint32_t aAddr = aBase + s * 32;
                uint32_t ah[2][4];
                ldm4(ah[0], aAddr);
                ldm4(ah[1], aAddr + 16 * A_STRIDE_B);

                uint32_t bh[4][2];
                const int fragIdx = ((ch * KSTEPS + s) * 8 + nw * 4);
                #pragma unroll
                for (int j = 0; j < 4; j++) {
                    uint2 vh = __ldg((const uint2*)(g_Bh + (fragIdx + j) * 256 + lane * 8));
                    bh[j][0] = vh.x; bh[j][1] = vh.y;
                }

                #pragma unroll
                for (int mt = 0; mt < 2; mt++)
                    #pragma unroll
                    for (int j = 0; j < 4; j++)
                        mma16816(d[mt][j], ah[mt], bh[j]);
            }

            // store staged next chunk into the other buffer, then one bar
            if (have_next) {
                const uint32_t hoff = sbase + (buf ^ 1) * ABUF_BYTES;
                #pragma unroll
                for (int k = 0; k < 10; k++)
                    sts128(hoff + (uint32_t)(srow[k] * A_STRIDE_B + scc[k] * 16), stage[k]);
            }
            __syncthreads();
            buf ^= 1;
        }

        // ---- epilogue: add fp32 constant, store ----
        #pragma unroll
        for (int mt = 0; mt < 2; mt++) {
            #pragma unroll
            for (int half = 0; half < 2; half++) {
                const long grow = tile_row0 + mw * 32 + mt * 16 + (lane >> 2) + half * 8;
                if (grow < n_rows) {
                    #pragma unroll
                    for (int j = 0; j < 4; j++) {
                        const int col = nw * 32 + j * 8 + (lane & 3) * 2;
                        float2 v;
                        v.x = d[mt][j][half * 2 + 0] + c0v[j][0];
                        v.y = d[mt][j][half * 2 + 1] + c0v[j][1];
                        *(float2*)(out + grow * HID + col) = v;
                    }
                }
            }
        }
    }
}

// ---------------------------------------------------------------- launch
extern "C" void kernel_launch(void* const* d_in, const int* in_sizes, int n_in,
                              void* d_out, int out_size)
{
    const float* x = (const float*)d_in[0];
    const float* W = (const float*)d_in[1];
    const float* b = (const float*)d_in[2];
    float* out = (float*)d_out;

    int n_rows = in_sizes[0] / IN_DIM;          // 131072
    if (n_rows > MAXROWS) n_rows = MAXROWS;     // capacity guard
    const int ntiles = (n_rows + TILE_M - 1) / TILE_M;
    const int grid = ntiles < NCTAS ? ntiles : NCTAS;

    cudaFuncSetAttribute(gemm_kernel,
                         cudaFuncAttributeMaxDynamicSharedMemorySize, SMEM_TOTAL);

    prep_kernel<<<(KS_TOTAL * 8 * 32 + 255) / 256, 256>>>(W, b);
    gen_kernel<<<2048, THREADS>>>(x, n_rows);
    gemm_kernel<<<grid, THREADS, SMEM_TOTAL>>>(out, n_rows, ntiles);
}